// round 8
// baseline (speedup 1.0000x reference)
#include <cuda_runtime.h>
#include <cstdint>

// Problem constants
#define C_DIM   64
#define HW      4096             // 64*64
#define N_PTS   131072           // B*H*W = 32*4096
#define K_CODES 1024
#define O_ELEMS 8388608          // B*C*H*W = 32*64*64*64  (2^23)
#define OFF_LOSS O_ELEMS
#define OFF_IDX  (O_ELEMS + 1)

// Argmin tiling: 128 points x 64 codes per tile, 128 threads, 8x8 microtile
#define BM 128
#define BK 64
#define TH 128
#define NKT (K_CODES / BK)       // 16

// Scratch (device globals: allocation-free)
__device__ __align__(16) float g_enorm[K_CODES];   // ||e_k||^2
__device__ __align__(16) float g_znorm[N_PTS];     // ||z_n||^2
__device__ int   g_idx[N_PTS];
__device__ float g_partial[O_ELEMS / 256];         // 32768 block partials

// ---------------------------------------------------------------------------
// Warp tree sum of 64 squares: lane t holds v[t]^2+v[t+32]^2, shfl_down tree.
// ---------------------------------------------------------------------------
__device__ __forceinline__ float warp_tree_sumsq(float a, float b) {
    float s = __fadd_rn(__fmul_rn(a, a), __fmul_rn(b, b));
    #pragma unroll
    for (int off = 16; off > 0; off >>= 1)
        s = __fadd_rn(s, __shfl_down_sync(0xffffffffu, s, off));
    return s;
}

// ---------------------------------------------------------------------------
// Kernel 0: codebook squared norms (one warp per code row)
// ---------------------------------------------------------------------------
__global__ void enorm_kernel(const float* __restrict__ emb) {
    int w = (blockIdx.x * blockDim.x + threadIdx.x) >> 5;
    int t = threadIdx.x & 31;
    if (w < K_CODES) {
        const float* r = emb + (size_t)w * C_DIM;
        float s = warp_tree_sumsq(r[t], r[t + 32]);
        if (t == 0) g_enorm[w] = s;
    }
}

// ---------------------------------------------------------------------------
// Kernel 1: point squared norms via staged [64ch x 32pt] tile (stride 33)
// ---------------------------------------------------------------------------
__global__ void znorm_kernel(const float* __restrict__ x) {
    __shared__ float tile[C_DIM * 33];
    const int p0  = blockIdx.x * 32;
    const int b   = p0 >> 12;
    const int hw0 = p0 & 4095;
    const float* xb = x + (size_t)b * C_DIM * HW + hw0;
    const int lane = threadIdx.x & 31, wid = threadIdx.x >> 5;

    for (int c = wid; c < C_DIM; c += 8)
        tile[c * 33 + lane] = xb[(size_t)c * HW + lane];
    __syncthreads();

    #pragma unroll
    for (int q = 0; q < 4; q++) {
        int p = wid * 4 + q;
        float s = warp_tree_sumsq(tile[lane * 33 + p], tile[(lane + 32) * 33 + p]);
        if (lane == 0) g_znorm[p0 + p] = s;
    }
}

// ---------------------------------------------------------------------------
// Kernel 2: argmin_k ( (||z||^2 - 2 z.e_k) + ||e_k||^2 ).
// Packed f32x2 FMA mainloop (validated index-identical to scalar in R6).
// Static smem 48KB: zs 32KB + es 16KB.
// ---------------------------------------------------------------------------
__global__ __launch_bounds__(TH, 4)
void argmin_kernel(const float* __restrict__ x, const float* __restrict__ emb) {
    __shared__ float zs[C_DIM * BM];   // [c][m]
    __shared__ float es[C_DIM * BK];   // [c][k]
    float* red_val = zs;               // aliased after mainloop
    int*   red_idx = reinterpret_cast<int*>(zs + 1024);

    const int tid = threadIdx.x;
    const int P0  = blockIdx.x * BM;
    const int b   = P0 >> 12;
    const int hw0 = P0 & 4095;
    const float* xbase = x + (size_t)b * C_DIM * HW + hw0;

    // load z tile: zs[c][m]; 4 warps, one c-row per warp per iter
    {
        int lane = tid & 31, w = tid >> 5;
        for (int c = w; c < C_DIM; c += 4) {
            float4 v = *reinterpret_cast<const float4*>(xbase + (size_t)c * HW + lane * 4);
            *reinterpret_cast<float4*>(zs + c * BM + lane * 4) = v;
        }
    }

    const int tck = tid & 7, tr = tid >> 3;   // 8 k-cols x 16 m-rows
    const int m0 = tr * 8, n0 = tck * 8;

    float4 znA = *reinterpret_cast<const float4*>(g_znorm + P0 + m0);
    float4 znB = *reinterpret_cast<const float4*>(g_znorm + P0 + m0 + 4);
    float zn[8] = { znA.x, znA.y, znA.z, znA.w, znB.x, znB.y, znB.z, znB.w };

    float minval[8];
    int   minidx[8];
    #pragma unroll
    for (int i = 0; i < 8; i++) { minval[i] = 3.0e38f; minidx[i] = 0; }

    for (int kt = 0; kt < NKT; kt++) {
        __syncthreads();   // readers done with previous es (covers zs on kt=0)
        // es[c][kk] = emb[(kt*64+kk)*64 + c]
        {
            int kk = tid >> 1, half = (tid & 1) * 32;
            const float4* erow =
                reinterpret_cast<const float4*>(emb + (size_t)(kt * BK + kk) * C_DIM + half);
            #pragma unroll
            for (int i = 0; i < 8; i++) {
                float4 v = erow[i];
                int c = half + i * 4;
                es[(c + 0) * BK + kk] = v.x;
                es[(c + 1) * BK + kk] = v.y;
                es[(c + 2) * BK + kk] = v.z;
                es[(c + 3) * BK + kk] = v.w;
            }
        }
        __syncthreads();

        unsigned long long acc[8][4];
        #pragma unroll
        for (int i = 0; i < 8; i++)
            #pragma unroll
            for (int j = 0; j < 4; j++) acc[i][j] = 0ull;   // {0.f,0.f}

        #pragma unroll 4
        for (int c = 0; c < C_DIM; c++) {
            float4 za = *reinterpret_cast<const float4*>(zs + c * BM + m0);
            float4 zb = *reinterpret_cast<const float4*>(zs + c * BM + m0 + 4);
            ulonglong2 eA = *reinterpret_cast<const ulonglong2*>(es + c * BK + n0);
            ulonglong2 eB = *reinterpret_cast<const ulonglong2*>(es + c * BK + n0 + 4);
            unsigned long long e2[4] = { eA.x, eA.y, eB.x, eB.y };
            float z[8] = { za.x, za.y, za.z, za.w, zb.x, zb.y, zb.z, zb.w };
            #pragma unroll
            for (int i = 0; i < 8; i++) {
                unsigned long long z2;
                unsigned int zu = __float_as_uint(z[i]);
                asm("mov.b64 %0, {%1, %1};" : "=l"(z2) : "r"(zu));
                #pragma unroll
                for (int j = 0; j < 4; j++)
                    asm("fma.rn.f32x2 %0, %1, %2, %0;"
                        : "+l"(acc[i][j]) : "l"(z2), "l"(e2[j]));
            }
        }

        // fold: v = (zn - 2*dot) + en, each step RN, ref association
        const int kbase = kt * BK + n0;
        float4 enA = __ldg(reinterpret_cast<const float4*>(g_enorm + kbase));
        float4 enB = __ldg(reinterpret_cast<const float4*>(g_enorm + kbase + 4));
        float en[8] = { enA.x, enA.y, enA.z, enA.w, enB.x, enB.y, enB.z, enB.w };
        #pragma unroll
        for (int i = 0; i < 8; i++) {
            #pragma unroll
            for (int j = 0; j < 4; j++) {
                float d0 = __uint_as_float((unsigned int)(acc[i][j] & 0xffffffffull));
                float d1 = __uint_as_float((unsigned int)(acc[i][j] >> 32));
                int k0 = kbase + 2 * j;
                float v0 = __fadd_rn(__fsub_rn(zn[i], __fmul_rn(2.0f, d0)), en[2 * j]);
                float v1 = __fadd_rn(__fsub_rn(zn[i], __fmul_rn(2.0f, d1)), en[2 * j + 1]);
                if (v0 < minval[i]) { minval[i] = v0; minidx[i] = k0; }
                if (v1 < minval[i]) { minval[i] = v1; minidx[i] = k0 + 1; }
            }
        }
    }

    __syncthreads();   // done with zs/es -> safe to alias reduction buffers
    #pragma unroll
    for (int i = 0; i < 8; i++) {
        red_val[(m0 + i) * 8 + tck] = minval[i];
        red_idx[(m0 + i) * 8 + tck] = minidx[i];
    }
    __syncthreads();

    {   // one thread per point row; ascending t keeps lowest index on ties
        float bv = red_val[tid * 8];
        int   bi = red_idx[tid * 8];
        #pragma unroll
        for (int t = 1; t < 8; t++) {
            float v  = red_val[tid * 8 + t];
            int   id = red_idx[tid * 8 + t];
            if (v < bv || (v == bv && id < bi)) { bv = v; bi = id; }
        }
        g_idx[P0 + tid] = bi;
    }
}

// ---------------------------------------------------------------------------
// Kernel 3: gather e, write o = x + (e-x), indices, per-block loss partials
// j in [0, 2^23): b = j>>18 (0..31), c = (j>>12)&63, hw = j&4095
// ---------------------------------------------------------------------------
__global__ void output_kernel(const float* __restrict__ x,
                              const float* __restrict__ emb,
                              float* __restrict__ out, int out_size) {
    int j  = blockIdx.x * 256 + threadIdx.x;
    int hw = j & 4095;
    int c  = (j >> 12) & 63;
    int b  = j >> 18;
    int n  = (b << 12) | hw;
    int idx = g_idx[n];
    float e  = emb[idx * C_DIM + c];
    float xv = x[j];
    float t  = __fsub_rn(e, xv);
    out[j] = __fadd_rn(xv, t);            // straight-through, ref fp ops
    if (c == 0 && (OFF_IDX + n) < out_size) out[OFF_IDX + n] = (float)idx;

    __shared__ float red[256];
    red[threadIdx.x] = t * t;
    __syncthreads();
    #pragma unroll
    for (int s = 128; s > 0; s >>= 1) {
        if (threadIdx.x < s) red[threadIdx.x] += red[threadIdx.x + s];
        __syncthreads();
    }
    if (threadIdx.x == 0) g_partial[blockIdx.x] = red[0];
}

// ---------------------------------------------------------------------------
// Kernel 4: deterministic final loss reduction: loss = m + 0.25*m
// ---------------------------------------------------------------------------
__global__ void loss_kernel(float* __restrict__ out, int out_size) {
    __shared__ float red[256];
    float s = 0.f;
    for (int i = threadIdx.x; i < O_ELEMS / 256; i += 256) s += g_partial[i];
    red[threadIdx.x] = s;
    __syncthreads();
    #pragma unroll
    for (int t = 128; t > 0; t >>= 1) {
        if (threadIdx.x < t) red[threadIdx.x] += red[threadIdx.x + t];
        __syncthreads();
    }
    if (threadIdx.x == 0 && OFF_LOSS < out_size) {
        float m = red[0] / (float)O_ELEMS;
        out[OFF_LOSS] = __fadd_rn(m, __fmul_rn(0.25f, m));
    }
}

// ---------------------------------------------------------------------------
extern "C" void kernel_launch(void* const* d_in, const int* in_sizes, int n_in,
                              void* d_out, int out_size) {
    // Robust input selection: x has 8388608 elems, emb has 65536.
    const float* p0 = (const float*)d_in[0];
    const float* p1 = (const float*)d_in[1];
    const float* x;
    const float* emb;
    if (in_sizes[0] == K_CODES * C_DIM) { emb = p0; x = p1; }
    else                                { x = p0; emb = p1; }
    float* out = (float*)d_out;

    enorm_kernel<<<K_CODES / 8, 256>>>(emb);
    znorm_kernel<<<N_PTS / 32, 256>>>(x);
    argmin_kernel<<<N_PTS / BM, TH>>>(x, emb);
    output_kernel<<<O_ELEMS / 256, 256>>>(x, emb, out, out_size);
    loss_kernel<<<1, 256>>>(out, out_size);
}